// round 2
// baseline (speedup 1.0000x reference)
#include <cuda_runtime.h>
#include <float.h>
#include <math.h>

#define NPTS 8192
#define CDIM 128
#define KNN  16
#define CS   16            // C / S
#define BN_INV 0.99999500003749973f   // 1/sqrt(1 + 1e-5)

// ---------------- scratch (static device globals; no allocation) ----------------
static __device__ float4 g_p4[NPTS];
static __device__ int    g_idx[NPTS * KNN];
static __device__ float  g_d2 [NPTS * KNN];
static __device__ float  g_xq [NPTS * CDIM];
static __device__ float  g_xk [NPTS * CDIM];
static __device__ float  g_xv [NPTS * CDIM];

// ---------------- kernel 0: pack p into float4 (x,y,z,|p|^2) ----------------
__global__ void prep_kernel(const float* __restrict__ p) {
    int i = blockIdx.x * blockDim.x + threadIdx.x;
    if (i < NPTS) {
        float x = p[i * 3 + 0], y = p[i * 3 + 1], z = p[i * 3 + 2];
        g_p4[i] = make_float4(x, y, z, x * x + y * y + z * z);
    }
}

// ---------------- kernel 1: KNN, TWO queries per block ----------------
// Each p4 point loaded once serves both queries (halves L2 traffic).
// Two independent 128-thread selection groups, synced by named barriers.
__global__ __launch_bounds__(256) void knn_kernel() {
    extern __shared__ float sdyn[];          // 2 * NPTS floats = 64 KB
    __shared__ float lm[256];
    __shared__ int   li[256];
    __shared__ float wm[2][4];
    __shared__ int   wi[2][4];
    __shared__ int   s_owner[2];

    const int t = threadIdx.x;
    const int b = blockIdx.x;

    const float4 q0 = g_p4[b * 2 + 0];
    const float4 q1 = g_p4[b * 2 + 1];
    float* sd0 = sdyn;
    float* sd1 = sdyn + NPTS;

    // shared distance pass: one p4 load -> two d2 (EXACT reference formula)
    #pragma unroll 4
    for (int j = t; j < NPTS; j += 256) {
        float4 pj = g_p4[j];
        sd0[j] = q0.w + pj.w - 2.0f * (q0.x * pj.x + q0.y * pj.y + q0.z * pj.z);
        sd1[j] = q1.w + pj.w - 2.0f * (q1.x * pj.x + q1.y * pj.y + q1.z * pj.z);
    }
    __syncthreads();

    const int g = t >> 7;             // group 0/1
    const int u = t & 127;            // tid within group
    const int n = b * 2 + g;
    float* sd = g ? sd1 : sd0;

    // per-thread local min over stripe {u, u+128, ...}
    float bv = FLT_MAX; int bi = -1;
    #pragma unroll 4
    for (int j = u; j < NPTS; j += 128) {
        float d = sd[j];
        if (d < bv || (d == bv && j < bi)) { bv = d; bi = j; }
    }
    lm[t] = bv; li[t] = bi;

    const int lane = t & 31;
    const int wg   = (t >> 5) & 3;    // warp within group
    const int barid = g + 1;          // named barriers 1 and 2

    for (int r = 0; r < KNN; ++r) {
        asm volatile("bar.sync %0, %1;" :: "r"(barid), "r"(128));
        // reduce 128 cached local minima (4 warps)
        float v = lm[t]; int vi = li[t];
        #pragma unroll
        for (int s = 16; s > 0; s >>= 1) {
            float ov = __shfl_down_sync(0xffffffffu, v, s);
            int   oi = __shfl_down_sync(0xffffffffu, vi, s);
            if (ov < v || (ov == v && oi < vi)) { v = ov; vi = oi; }
        }
        if (lane == 0) { wm[g][wg] = v; wi[g][wg] = vi; }
        asm volatile("bar.sync %0, %1;" :: "r"(barid), "r"(128));
        if (u == 0) {
            float fv = wm[g][0]; int fi = wi[g][0];
            #pragma unroll
            for (int w2 = 1; w2 < 4; ++w2)
                if (wm[g][w2] < fv || (wm[g][w2] == fv && wi[g][w2] < fi)) { fv = wm[g][w2]; fi = wi[g][w2]; }
            g_idx[n * KNN + r] = fi;
            g_d2 [n * KNN + r] = fv;
            sd[fi] = FLT_MAX;
            s_owner[g] = fi & 127;
        }
        asm volatile("bar.sync %0, %1;" :: "r"(barid), "r"(128));
        if (u == s_owner[g]) {
            float nb = FLT_MAX; int ni = -1;
            #pragma unroll 4
            for (int j = u; j < NPTS; j += 128) {
                float d = sd[j];
                if (d < nb || (d == nb && j < ni)) { nb = d; ni = j; }
            }
            lm[t] = nb; li[t] = ni;
        }
    }
}

// ---------------- kernel 2: three 8192x128x128 fp32 GEMMs (xq,xk,xv) ----------------
__global__ __launch_bounds__(256, 2) void gemm3_kernel(
    const float* __restrict__ x,
    const float* __restrict__ Wq, const float* __restrict__ bq,
    const float* __restrict__ Wk, const float* __restrict__ bk,
    const float* __restrict__ Wv, const float* __restrict__ bv)
{
    __shared__ float  As[64][17];
    __shared__ float4 Bs[16][32];   // 16 x 128 floats

    const float* W; const float* b; float* out;
    if (blockIdx.y == 0)      { W = Wq; b = bq; out = g_xq; }
    else if (blockIdx.y == 1) { W = Wk; b = bk; out = g_xk; }
    else                      { W = Wv; b = bv; out = g_xv; }

    const int t  = threadIdx.x;
    const int tx = t & 15, ty = t >> 4;
    const int row0 = blockIdx.x * 64;

    float acc[4][8];
    #pragma unroll
    for (int i = 0; i < 4; ++i)
        #pragma unroll
        for (int j = 0; j < 8; ++j) acc[i][j] = 0.0f;

    for (int k0 = 0; k0 < CDIM; k0 += 16) {
        #pragma unroll
        for (int i = 0; i < 4; ++i) {
            int lin = t + i * 256;
            int r = lin >> 4, kk = lin & 15;
            As[r][kk] = x[(row0 + r) * CDIM + k0 + kk];
        }
        #pragma unroll
        for (int i = 0; i < 8; ++i) {
            int lin = t + i * 256;
            int kk = lin >> 7, col = lin & 127;
            ((float*)Bs)[kk * 128 + col] = W[(k0 + kk) * CDIM + col];
        }
        __syncthreads();
        #pragma unroll
        for (int kk = 0; kk < 16; ++kk) {
            float a[4];
            #pragma unroll
            for (int i = 0; i < 4; ++i) a[i] = As[ty * 4 + i][kk];
            float4 b0 = Bs[kk][tx * 2 + 0];
            float4 b1 = Bs[kk][tx * 2 + 1];
            float bb[8] = {b0.x, b0.y, b0.z, b0.w, b1.x, b1.y, b1.z, b1.w};
            #pragma unroll
            for (int i = 0; i < 4; ++i)
                #pragma unroll
                for (int j = 0; j < 8; ++j)
                    acc[i][j] = fmaf(a[i], bb[j], acc[i][j]);
        }
        __syncthreads();
    }
    #pragma unroll
    for (int i = 0; i < 4; ++i) {
        int r = row0 + ty * 4 + i;
        #pragma unroll
        for (int j = 0; j < 8; ++j) {
            int c = tx * 8 + j;
            out[r * CDIM + c] = acc[i][j] + __ldg(&b[c]);
        }
    }
}

// ---------------- kernel 3: attn v2 — warp owns 2 neighbors, w0 in registers ----------------
#define PITCH 132   // 132*4 = 528 bytes, 16B aligned
__global__ __launch_bounds__(256) void attn_kernel(
    float* __restrict__ outp,
    const float* __restrict__ Wp1, const float* __restrict__ bp1,
    const float* __restrict__ g1,  const float* __restrict__ be1,
    const float* __restrict__ Wp2, const float* __restrict__ bp2,
    const float* __restrict__ g2,  const float* __restrict__ be2,
    const float* __restrict__ Ww1, const float* __restrict__ bw1,
    const float* __restrict__ g3,  const float* __restrict__ be3,
    const float* __restrict__ Ww2, const float* __restrict__ bw2)
{
    __shared__ float s_w1t[CS][PITCH];     // Ww1 transposed: [j][c]
    __shared__ float s_v  [KNN][PITCH];    // v = xv*dw + pr
    __shared__ float s_ww2[CS][CS];
    __shared__ float s_pr1[KNN][4];
    __shared__ float s_dw [KNN];
    __shared__ int   s_id [KNN];
    __shared__ float s_h  [KNN][17];
    __shared__ float s_w2 [KNN][17];

    const int n = blockIdx.x;
    const int t = threadIdx.x;
    const int w = t >> 5;       // warp 0..7
    const int l = t & 31;       // lane

    // stage Ww1^T and Ww2
    #pragma unroll
    for (int i = t; i < CDIM * CS; i += 256) {
        int c = i >> 4, j = i & 15;
        s_w1t[j][c] = Ww1[i];
    }
    s_ww2[t >> 4][t & 15] = Ww2[t];

    // phase A: per-neighbor scalars
    if (t < KNN) {
        int id = g_idx[n * KNN + t];
        s_id[t] = id;
        float d2 = g_d2[n * KNN + t];
        s_dw[t] = expf(-sqrtf(fmaxf(d2, 0.0f)));
        float4 pq = g_p4[n], pj = g_p4[id];
        float rx = pj.x - pq.x, ry = pj.y - pq.y, rz = pj.z - pq.z;
        #pragma unroll
        for (int j = 0; j < 3; ++j) {
            float vv = rx * Wp1[0 * 3 + j] + ry * Wp1[1 * 3 + j] + rz * Wp1[2 * 3 + j] + bp1[j];
            vv = vv * (g1[j] * BN_INV) + be1[j];
            s_pr1[t][j] = fmaxf(vv, 0.0f);
        }
    }
    __syncthreads();

    // phase B: warp w handles neighbors k0=2w, k1=2w+1; lane l owns channels 4l..4l+3
    const int c0 = 4 * l;
    const float4 xq4  = *(const float4*)&g_xq[n * CDIM + c0];
    const float4 wpA  = *(const float4*)&Wp2[0 * CDIM + c0];
    const float4 wpB  = *(const float4*)&Wp2[1 * CDIM + c0];
    const float4 wpC  = *(const float4*)&Wp2[2 * CDIM + c0];
    const float4 bp4  = *(const float4*)&bp2[c0];
    float4 sc24 = *(const float4*)&g2[c0];
    sc24.x *= BN_INV; sc24.y *= BN_INV; sc24.z *= BN_INV; sc24.w *= BN_INV;
    const float4 be24 = *(const float4*)&be2[c0];

    const int k0 = 2 * w, k1 = 2 * w + 1;
    float4 w0a, w0b;
    {
        // --- neighbor k0 ---
        int id = s_id[k0];
        float4 xk4 = *(const float4*)&g_xk[id * CDIM + c0];
        float4 xv4 = *(const float4*)&g_xv[id * CDIM + c0];
        float a0 = s_pr1[k0][0], a1 = s_pr1[k0][1], a2 = s_pr1[k0][2], dwv = s_dw[k0];
        float4 pr;
        pr.x = fmaf(a0, wpA.x, fmaf(a1, wpB.x, fmaf(a2, wpC.x, bp4.x)));
        pr.y = fmaf(a0, wpA.y, fmaf(a1, wpB.y, fmaf(a2, wpC.y, bp4.y)));
        pr.z = fmaf(a0, wpA.z, fmaf(a1, wpB.z, fmaf(a2, wpC.z, bp4.z)));
        pr.w = fmaf(a0, wpA.w, fmaf(a1, wpB.w, fmaf(a2, wpC.w, bp4.w)));
        float4 v4;
        v4.x = fmaf(xv4.x, dwv, pr.x); v4.y = fmaf(xv4.y, dwv, pr.y);
        v4.z = fmaf(xv4.z, dwv, pr.z); v4.w = fmaf(xv4.w, dwv, pr.w);
        *(float4*)&s_v[k0][c0] = v4;
        w0a.x = fmaxf(fmaf(xq4.x - xk4.x + pr.x, sc24.x, be24.x), 0.0f);
        w0a.y = fmaxf(fmaf(xq4.y - xk4.y + pr.y, sc24.y, be24.y), 0.0f);
        w0a.z = fmaxf(fmaf(xq4.z - xk4.z + pr.z, sc24.z, be24.z), 0.0f);
        w0a.w = fmaxf(fmaf(xq4.w - xk4.w + pr.w, sc24.w, be24.w), 0.0f);
        // --- neighbor k1 ---
        id = s_id[k1];
        xk4 = *(const float4*)&g_xk[id * CDIM + c0];
        xv4 = *(const float4*)&g_xv[id * CDIM + c0];
        a0 = s_pr1[k1][0]; a1 = s_pr1[k1][1]; a2 = s_pr1[k1][2]; dwv = s_dw[k1];
        pr.x = fmaf(a0, wpA.x, fmaf(a1, wpB.x, fmaf(a2, wpC.x, bp4.x)));
        pr.y = fmaf(a0, wpA.y, fmaf(a1, wpB.y, fmaf(a2, wpC.y, bp4.y)));
        pr.z = fmaf(a0, wpA.z, fmaf(a1, wpB.z, fmaf(a2, wpC.z, bp4.z)));
        pr.w = fmaf(a0, wpA.w, fmaf(a1, wpB.w, fmaf(a2, wpC.w, bp4.w)));
        v4.x = fmaf(xv4.x, dwv, pr.x); v4.y = fmaf(xv4.y, dwv, pr.y);
        v4.z = fmaf(xv4.z, dwv, pr.z); v4.w = fmaf(xv4.w, dwv, pr.w);
        *(float4*)&s_v[k1][c0] = v4;
        w0b.x = fmaxf(fmaf(xq4.x - xk4.x + pr.x, sc24.x, be24.x), 0.0f);
        w0b.y = fmaxf(fmaf(xq4.y - xk4.y + pr.y, sc24.y, be24.y), 0.0f);
        w0b.z = fmaxf(fmaf(xq4.z - xk4.z + pr.z, sc24.z, be24.z), 0.0f);
        w0b.w = fmaxf(fmaf(xq4.w - xk4.w + pr.w, sc24.w, be24.w), 0.0f);
    }

    // partial products: Ww1^T read ONCE per warp (16 LDS.128), w0 stays in regs
    float pa[16], pb[16];
    #pragma unroll
    for (int j = 0; j < 16; ++j) {
        float4 wv = *(const float4*)&s_w1t[j][c0];
        pa[j] = w0a.x * wv.x + w0a.y * wv.y + w0a.z * wv.z + w0a.w * wv.w;
        pb[j] = w0b.x * wv.x + w0b.y * wv.y + w0b.z * wv.z + w0b.w * wv.w;
    }

    // value-splitting butterfly reduction over 32 lanes:
    // final: lane l holds sum for k = 2w + (l>>4), j = l&15
    float red[16];
    #pragma unroll
    for (int j = 0; j < 16; ++j) {
        float send = (l < 16) ? pb[j] : pa[j];
        float recv = __shfl_xor_sync(0xffffffffu, send, 16);
        red[j] = ((l < 16) ? pa[j] : pb[j]) + recv;
    }
    #pragma unroll
    for (int j = 0; j < 8; ++j) {
        bool hi = (l & 8) != 0;
        float send = hi ? red[j] : red[j + 8];
        float recv = __shfl_xor_sync(0xffffffffu, send, 8);
        red[j] = (hi ? red[j + 8] : red[j]) + recv;
    }
    #pragma unroll
    for (int j = 0; j < 4; ++j) {
        bool hi = (l & 4) != 0;
        float send = hi ? red[j] : red[j + 4];
        float recv = __shfl_xor_sync(0xffffffffu, send, 4);
        red[j] = (hi ? red[j + 4] : red[j]) + recv;
    }
    #pragma unroll
    for (int j = 0; j < 2; ++j) {
        bool hi = (l & 2) != 0;
        float send = hi ? red[j] : red[j + 2];
        float recv = __shfl_xor_sync(0xffffffffu, send, 2);
        red[j] = (hi ? red[j + 2] : red[j]) + recv;
    }
    {
        bool hi = (l & 1) != 0;
        float send = hi ? red[0] : red[1];
        float recv = __shfl_xor_sync(0xffffffffu, send, 1);
        red[0] = (hi ? red[1] : red[0]) + recv;
    }
    {
        const int jj = l & 15;
        const int kk = 2 * w + (l >> 4);
        float val = red[0] + __ldg(&bw1[jj]);
        s_h[kk][jj] = fmaxf(fmaf(val, __ldg(&g3[jj]) * BN_INV, __ldg(&be3[jj])), 0.0f);
    }
    __syncthreads();

    // w2 = h @ Ww2 (16x16), then softmax over k
    const int k = t >> 4, j = t & 15;
    {
        float acc2 = bw2[j];
        #pragma unroll
        for (int j2 = 0; j2 < CS; ++j2)
            acc2 = fmaf(s_h[k][j2], s_ww2[j2][j], acc2);
        s_w2[k][j] = acc2;
    }
    __syncthreads();
    {
        float m = -FLT_MAX;
        #pragma unroll
        for (int k2 = 0; k2 < KNN; ++k2) m = fmaxf(m, s_w2[k2][j]);
        s_h[k][j] = expf(s_w2[k][j] - m);
    }
    __syncthreads();
    {
        float ssum = 0.0f;
        #pragma unroll
        for (int k2 = 0; k2 < KNN; ++k2) ssum += s_h[k2][j];
        s_w2[k][j] = s_h[k][j] / ssum;
    }
    __syncthreads();

    // phase D: out[c] = sum_k v[k][c] * w[k][c&15]
    if (t < CDIM) {
        const int c = t, jj = t & 15;
        float o = 0.0f;
        #pragma unroll
        for (int k2 = 0; k2 < KNN; ++k2)
            o = fmaf(s_v[k2][c], s_w2[k2][jj], o);
        outp[n * CDIM + c] = o;
    }
}

// ---------------- launch ----------------
extern "C" void kernel_launch(void* const* d_in, const int* in_sizes, int n_in,
                              void* d_out, int out_size) {
    const float* p   = (const float*)d_in[0];
    const float* x   = (const float*)d_in[1];
    const float* Wq  = (const float*)d_in[2];
    const float* bq  = (const float*)d_in[3];
    const float* Wk  = (const float*)d_in[4];
    const float* bk  = (const float*)d_in[5];
    const float* Wv  = (const float*)d_in[6];
    const float* bv  = (const float*)d_in[7];
    const float* Wp1 = (const float*)d_in[8];
    const float* bp1 = (const float*)d_in[9];
    const float* g1  = (const float*)d_in[10];
    const float* be1 = (const float*)d_in[11];
    const float* Wp2 = (const float*)d_in[12];
    const float* bp2 = (const float*)d_in[13];
    const float* g2  = (const float*)d_in[14];
    const float* be2 = (const float*)d_in[15];
    const float* Ww1 = (const float*)d_in[16];
    const float* bw1 = (const float*)d_in[17];
    const float* g3  = (const float*)d_in[18];
    const float* be3 = (const float*)d_in[19];
    const float* Ww2 = (const float*)d_in[20];
    const float* bw2 = (const float*)d_in[21];
    float* outp = (float*)d_out;

    cudaFuncSetAttribute(knn_kernel, cudaFuncAttributeMaxDynamicSharedMemorySize,
                         2 * NPTS * (int)sizeof(float));

    prep_kernel<<<(NPTS + 255) / 256, 256>>>(p);
    gemm3_kernel<<<dim3(NPTS / 64, 3), 256>>>(x, Wq, bq, Wk, bk, Wv, bv);
    knn_kernel<<<NPTS / 2, 256, 2 * NPTS * (int)sizeof(float)>>>();
    attn_kernel<<<NPTS, 256>>>(outp, Wp1, bp1, g1, be1, Wp2, bp2,
                               g2, be2, Ww1, bw1, g3, be3, Ww2, bw2);
}

// round 3
// speedup vs baseline: 2.0491x; 2.0491x over previous
#include <cuda_runtime.h>
#include <float.h>
#include <math.h>

#define NPTS 8192
#define CDIM 128
#define KNN  16
#define CS   16            // C / S
#define BN_INV 0.99999500003749973f   // 1/sqrt(1 + 1e-5)
#define TS   2048          // knn point tile (32 KB)

// ---------------- scratch (static device globals; no allocation) ----------------
static __device__ float4 g_p4[NPTS];
static __device__ int    g_idx[NPTS * KNN];
static __device__ float  g_d2 [NPTS * KNN];
static __device__ float  g_xq [NPTS * CDIM];
static __device__ float  g_xk [NPTS * CDIM];
static __device__ float  g_xv [NPTS * CDIM];

// ---------------- kernel 0: pack p into float4 (x,y,z,|p|^2) ----------------
__global__ void prep_kernel(const float* __restrict__ p) {
    int i = blockIdx.x * blockDim.x + threadIdx.x;
    if (i < NPTS) {
        float x = p[i * 3 + 0], y = p[i * 3 + 1], z = p[i * 3 + 2];
        g_p4[i] = make_float4(x, y, z, x * x + y * y + z * z);
    }
}

// ---------------- kernel 1: KNN v4 — one warp per query, streaming top-16 ----------------
// Distributed sorted top-16 across lanes 0..15 (ascending by (d2, idx) lex).
// Steady state: ~13 warp-instr per 32-point chunk; insertions are rare and ~12 instr.
__global__ __launch_bounds__(256) void knn_kernel() {
    __shared__ float4 s_tile[TS];

    const int t    = threadIdx.x;
    const int w    = t >> 5;
    const int lane = t & 31;
    const int n    = blockIdx.x * 8 + w;

    const float4 q = g_p4[n];

    float kv = FLT_MAX;          // this lane's kept value (lanes 0..15 meaningful)
    int   ki = 0x7FFFFFFF;
    float kthv = FLT_MAX;        // current 16th (lane 15) value, warp-uniform
    int   kthi = 0x7FFFFFFF;

    for (int tb = 0; tb < NPTS; tb += TS) {
        __syncthreads();
        #pragma unroll
        for (int i = 0; i < TS / 256; ++i)
            s_tile[t + i * 256] = g_p4[tb + t + i * 256];
        __syncthreads();

        #pragma unroll 4
        for (int c = 0; c < TS / 32; ++c) {
            const int jl = c * 32 + lane;
            const float4 pj = s_tile[jl];
            float m = q.x * pj.x;
            m = fmaf(q.y, pj.y, m);
            m = fmaf(q.z, pj.z, m);
            const float d = (q.w + pj.w) - 2.0f * m;
            const int j = tb + jl;

            bool pass = (d < kthv) || (d == kthv && j < kthi);
            unsigned mask = __ballot_sync(0xffffffffu, pass);
            while (mask) {
                const int src = __ffs(mask) - 1;
                mask &= mask - 1;
                const float cv = __shfl_sync(0xffffffffu, d, src);
                const int   cj = __shfl_sync(0xffffffffu, j, src);
                // skip if list already improved past this candidate (uniform branch)
                if (!((cv < kthv) || (cv == kthv && cj < kthi))) continue;
                // insertion position = #kept lexicographically smaller
                const bool lt = (kv < cv) || (kv == cv && ki < cj);
                const int pos = __popc(__ballot_sync(0xffffffffu, lt) & 0xFFFFu);
                const float upv = __shfl_up_sync(0xffffffffu, kv, 1);
                const int   upi = __shfl_up_sync(0xffffffffu, ki, 1);
                if (lane >= pos && lane < 16) {
                    if (lane == pos) { kv = cv; ki = cj; }
                    else             { kv = upv; ki = upi; }
                }
                kthv = __shfl_sync(0xffffffffu, kv, 15);
                kthi = __shfl_sync(0xffffffffu, ki, 15);
            }
        }
    }

    if (lane < KNN) {
        g_d2 [n * KNN + lane] = kv;
        g_idx[n * KNN + lane] = ki;
    }
}

// ---------------- kernel 2: three 8192x128x128 fp32 GEMMs (xq,xk,xv) ----------------
__global__ __launch_bounds__(256, 2) void gemm3_kernel(
    const float* __restrict__ x,
    const float* __restrict__ Wq, const float* __restrict__ bq,
    const float* __restrict__ Wk, const float* __restrict__ bk,
    const float* __restrict__ Wv, const float* __restrict__ bv)
{
    __shared__ float  As[64][17];
    __shared__ float4 Bs[16][32];   // 16 x 128 floats

    const float* W; const float* b; float* out;
    if (blockIdx.y == 0)      { W = Wq; b = bq; out = g_xq; }
    else if (blockIdx.y == 1) { W = Wk; b = bk; out = g_xk; }
    else                      { W = Wv; b = bv; out = g_xv; }

    const int t  = threadIdx.x;
    const int tx = t & 15, ty = t >> 4;
    const int row0 = blockIdx.x * 64;

    float acc[4][8];
    #pragma unroll
    for (int i = 0; i < 4; ++i)
        #pragma unroll
        for (int j = 0; j < 8; ++j) acc[i][j] = 0.0f;

    for (int k0 = 0; k0 < CDIM; k0 += 16) {
        #pragma unroll
        for (int i = 0; i < 4; ++i) {
            int lin = t + i * 256;
            int r = lin >> 4, kk = lin & 15;
            As[r][kk] = x[(row0 + r) * CDIM + k0 + kk];
        }
        #pragma unroll
        for (int i = 0; i < 8; ++i) {
            int lin = t + i * 256;
            int kk = lin >> 7, col = lin & 127;
            ((float*)Bs)[kk * 128 + col] = W[(k0 + kk) * CDIM + col];
        }
        __syncthreads();
        #pragma unroll
        for (int kk = 0; kk < 16; ++kk) {
            float a[4];
            #pragma unroll
            for (int i = 0; i < 4; ++i) a[i] = As[ty * 4 + i][kk];
            float4 b0 = Bs[kk][tx * 2 + 0];
            float4 b1 = Bs[kk][tx * 2 + 1];
            float bb[8] = {b0.x, b0.y, b0.z, b0.w, b1.x, b1.y, b1.z, b1.w};
            #pragma unroll
            for (int i = 0; i < 4; ++i)
                #pragma unroll
                for (int j = 0; j < 8; ++j)
                    acc[i][j] = fmaf(a[i], bb[j], acc[i][j]);
        }
        __syncthreads();
    }
    #pragma unroll
    for (int i = 0; i < 4; ++i) {
        int r = row0 + ty * 4 + i;
        #pragma unroll
        for (int j = 0; j < 8; ++j) {
            int c = tx * 8 + j;
            out[r * CDIM + c] = acc[i][j] + __ldg(&b[c]);
        }
    }
}

// ---------------- kernel 3: attn v2 — warp owns 2 neighbors, w0 in registers ----------------
#define PITCH 132   // 132*4 = 528 bytes, 16B aligned
__global__ __launch_bounds__(256) void attn_kernel(
    float* __restrict__ outp,
    const float* __restrict__ Wp1, const float* __restrict__ bp1,
    const float* __restrict__ g1,  const float* __restrict__ be1,
    const float* __restrict__ Wp2, const float* __restrict__ bp2,
    const float* __restrict__ g2,  const float* __restrict__ be2,
    const float* __restrict__ Ww1, const float* __restrict__ bw1,
    const float* __restrict__ g3,  const float* __restrict__ be3,
    const float* __restrict__ Ww2, const float* __restrict__ bw2)
{
    __shared__ float s_w1t[CS][PITCH];     // Ww1 transposed: [j][c]
    __shared__ float s_v  [KNN][PITCH];    // v = xv*dw + pr
    __shared__ float s_ww2[CS][CS];
    __shared__ float s_pr1[KNN][4];
    __shared__ float s_dw [KNN];
    __shared__ int   s_id [KNN];
    __shared__ float s_h  [KNN][17];
    __shared__ float s_w2 [KNN][17];

    const int n = blockIdx.x;
    const int t = threadIdx.x;
    const int w = t >> 5;       // warp 0..7
    const int l = t & 31;       // lane

    // stage Ww1^T and Ww2
    #pragma unroll
    for (int i = t; i < CDIM * CS; i += 256) {
        int c = i >> 4, j = i & 15;
        s_w1t[j][c] = Ww1[i];
    }
    s_ww2[t >> 4][t & 15] = Ww2[t];

    // phase A: per-neighbor scalars
    if (t < KNN) {
        int id = g_idx[n * KNN + t];
        s_id[t] = id;
        float d2 = g_d2[n * KNN + t];
        s_dw[t] = expf(-sqrtf(fmaxf(d2, 0.0f)));
        float4 pq = g_p4[n], pj = g_p4[id];
        float rx = pj.x - pq.x, ry = pj.y - pq.y, rz = pj.z - pq.z;
        #pragma unroll
        for (int j = 0; j < 3; ++j) {
            float vv = rx * Wp1[0 * 3 + j] + ry * Wp1[1 * 3 + j] + rz * Wp1[2 * 3 + j] + bp1[j];
            vv = vv * (g1[j] * BN_INV) + be1[j];
            s_pr1[t][j] = fmaxf(vv, 0.0f);
        }
    }
    __syncthreads();

    // phase B: warp w handles neighbors k0=2w, k1=2w+1; lane l owns channels 4l..4l+3
    const int c0 = 4 * l;
    const float4 xq4  = *(const float4*)&g_xq[n * CDIM + c0];
    const float4 wpA  = *(const float4*)&Wp2[0 * CDIM + c0];
    const float4 wpB  = *(const float4*)&Wp2[1 * CDIM + c0];
    const float4 wpC  = *(const float4*)&Wp2[2 * CDIM + c0];
    const float4 bp4  = *(const float4*)&bp2[c0];
    float4 sc24 = *(const float4*)&g2[c0];
    sc24.x *= BN_INV; sc24.y *= BN_INV; sc24.z *= BN_INV; sc24.w *= BN_INV;
    const float4 be24 = *(const float4*)&be2[c0];

    const int k0 = 2 * w, k1 = 2 * w + 1;
    float4 w0a, w0b;
    {
        // --- neighbor k0 ---
        int id = s_id[k0];
        float4 xk4 = *(const float4*)&g_xk[id * CDIM + c0];
        float4 xv4 = *(const float4*)&g_xv[id * CDIM + c0];
        float a0 = s_pr1[k0][0], a1 = s_pr1[k0][1], a2 = s_pr1[k0][2], dwv = s_dw[k0];
        float4 pr;
        pr.x = fmaf(a0, wpA.x, fmaf(a1, wpB.x, fmaf(a2, wpC.x, bp4.x)));
        pr.y = fmaf(a0, wpA.y, fmaf(a1, wpB.y, fmaf(a2, wpC.y, bp4.y)));
        pr.z = fmaf(a0, wpA.z, fmaf(a1, wpB.z, fmaf(a2, wpC.z, bp4.z)));
        pr.w = fmaf(a0, wpA.w, fmaf(a1, wpB.w, fmaf(a2, wpC.w, bp4.w)));
        float4 v4;
        v4.x = fmaf(xv4.x, dwv, pr.x); v4.y = fmaf(xv4.y, dwv, pr.y);
        v4.z = fmaf(xv4.z, dwv, pr.z); v4.w = fmaf(xv4.w, dwv, pr.w);
        *(float4*)&s_v[k0][c0] = v4;
        w0a.x = fmaxf(fmaf(xq4.x - xk4.x + pr.x, sc24.x, be24.x), 0.0f);
        w0a.y = fmaxf(fmaf(xq4.y - xk4.y + pr.y, sc24.y, be24.y), 0.0f);
        w0a.z = fmaxf(fmaf(xq4.z - xk4.z + pr.z, sc24.z, be24.z), 0.0f);
        w0a.w = fmaxf(fmaf(xq4.w - xk4.w + pr.w, sc24.w, be24.w), 0.0f);
        // --- neighbor k1 ---
        id = s_id[k1];
        xk4 = *(const float4*)&g_xk[id * CDIM + c0];
        xv4 = *(const float4*)&g_xv[id * CDIM + c0];
        a0 = s_pr1[k1][0]; a1 = s_pr1[k1][1]; a2 = s_pr1[k1][2]; dwv = s_dw[k1];
        pr.x = fmaf(a0, wpA.x, fmaf(a1, wpB.x, fmaf(a2, wpC.x, bp4.x)));
        pr.y = fmaf(a0, wpA.y, fmaf(a1, wpB.y, fmaf(a2, wpC.y, bp4.y)));
        pr.z = fmaf(a0, wpA.z, fmaf(a1, wpB.z, fmaf(a2, wpC.z, bp4.z)));
        pr.w = fmaf(a0, wpA.w, fmaf(a1, wpB.w, fmaf(a2, wpC.w, bp4.w)));
        v4.x = fmaf(xv4.x, dwv, pr.x); v4.y = fmaf(xv4.y, dwv, pr.y);
        v4.z = fmaf(xv4.z, dwv, pr.z); v4.w = fmaf(xv4.w, dwv, pr.w);
        *(float4*)&s_v[k1][c0] = v4;
        w0b.x = fmaxf(fmaf(xq4.x - xk4.x + pr.x, sc24.x, be24.x), 0.0f);
        w0b.y = fmaxf(fmaf(xq4.y - xk4.y + pr.y, sc24.y, be24.y), 0.0f);
        w0b.z = fmaxf(fmaf(xq4.z - xk4.z + pr.z, sc24.z, be24.z), 0.0f);
        w0b.w = fmaxf(fmaf(xq4.w - xk4.w + pr.w, sc24.w, be24.w), 0.0f);
    }

    // partial products: Ww1^T read ONCE per warp (16 LDS.128), w0 stays in regs
    float pa[16], pb[16];
    #pragma unroll
    for (int j = 0; j < 16; ++j) {
        float4 wv = *(const float4*)&s_w1t[j][c0];
        pa[j] = w0a.x * wv.x + w0a.y * wv.y + w0a.z * wv.z + w0a.w * wv.w;
        pb[j] = w0b.x * wv.x + w0b.y * wv.y + w0b.z * wv.z + w0b.w * wv.w;
    }

    // value-splitting butterfly reduction over 32 lanes:
    // final: lane l holds sum for k = 2w + (l>>4), j = l&15
    float red[16];
    #pragma unroll
    for (int j = 0; j < 16; ++j) {
        float send = (l < 16) ? pb[j] : pa[j];
        float recv = __shfl_xor_sync(0xffffffffu, send, 16);
        red[j] = ((l < 16) ? pa[j] : pb[j]) + recv;
    }
    #pragma unroll
    for (int j = 0; j < 8; ++j) {
        bool hi = (l & 8) != 0;
        float send = hi ? red[j] : red[j + 8];
        float recv = __shfl_xor_sync(0xffffffffu, send, 8);
        red[j] = (hi ? red[j + 8] : red[j]) + recv;
    }
    #pragma unroll
    for (int j = 0; j < 4; ++j) {
        bool hi = (l & 4) != 0;
        float send = hi ? red[j] : red[j + 4];
        float recv = __shfl_xor_sync(0xffffffffu, send, 4);
        red[j] = (hi ? red[j + 4] : red[j]) + recv;
    }
    #pragma unroll
    for (int j = 0; j < 2; ++j) {
        bool hi = (l & 2) != 0;
        float send = hi ? red[j] : red[j + 2];
        float recv = __shfl_xor_sync(0xffffffffu, send, 2);
        red[j] = (hi ? red[j + 2] : red[j]) + recv;
    }
    {
        bool hi = (l & 1) != 0;
        float send = hi ? red[0] : red[1];
        float recv = __shfl_xor_sync(0xffffffffu, send, 1);
        red[0] = (hi ? red[1] : red[0]) + recv;
    }
    {
        const int jj = l & 15;
        const int kk = 2 * w + (l >> 4);
        float val = red[0] + __ldg(&bw1[jj]);
        s_h[kk][jj] = fmaxf(fmaf(val, __ldg(&g3[jj]) * BN_INV, __ldg(&be3[jj])), 0.0f);
    }
    __syncthreads();

    // w2 = h @ Ww2 (16x16), then softmax over k
    const int k = t >> 4, j = t & 15;
    {
        float acc2 = bw2[j];
        #pragma unroll
        for (int j2 = 0; j2 < CS; ++j2)
            acc2 = fmaf(s_h[k][j2], s_ww2[j2][j], acc2);
        s_w2[k][j] = acc2;
    }
    __syncthreads();
    {
        float m = -FLT_MAX;
        #pragma unroll
        for (int k2 = 0; k2 < KNN; ++k2) m = fmaxf(m, s_w2[k2][j]);
        s_h[k][j] = expf(s_w2[k][j] - m);
    }
    __syncthreads();
    {
        float ssum = 0.0f;
        #pragma unroll
        for (int k2 = 0; k2 < KNN; ++k2) ssum += s_h[k2][j];
        s_w2[k][j] = s_h[k][j] / ssum;
    }
    __syncthreads();

    // phase D: out[c] = sum_k v[k][c] * w[k][c&15]
    if (t < CDIM) {
        const int c = t, jj = t & 15;
        float o = 0.0f;
        #pragma unroll
        for (int k2 = 0; k2 < KNN; ++k2)
            o = fmaf(s_v[k2][c], s_w2[k2][jj], o);
        outp[n * CDIM + c] = o;
    }
}

// ---------------- launch ----------------
extern "C" void kernel_launch(void* const* d_in, const int* in_sizes, int n_in,
                              void* d_out, int out_size) {
    const float* p   = (const float*)d_in[0];
    const float* x   = (const float*)d_in[1];
    const float* Wq  = (const float*)d_in[2];
    const float* bq  = (const float*)d_in[3];
    const float* Wk  = (const float*)d_in[4];
    const float* bk  = (const float*)d_in[5];
    const float* Wv  = (const float*)d_in[6];
    const float* bv  = (const float*)d_in[7];
    const float* Wp1 = (const float*)d_in[8];
    const float* bp1 = (const float*)d_in[9];
    const float* g1  = (const float*)d_in[10];
    const float* be1 = (const float*)d_in[11];
    const float* Wp2 = (const float*)d_in[12];
    const float* bp2 = (const float*)d_in[13];
    const float* g2  = (const float*)d_in[14];
    const float* be2 = (const float*)d_in[15];
    const float* Ww1 = (const float*)d_in[16];
    const float* bw1 = (const float*)d_in[17];
    const float* g3  = (const float*)d_in[18];
    const float* be3 = (const float*)d_in[19];
    const float* Ww2 = (const float*)d_in[20];
    const float* bw2 = (const float*)d_in[21];
    float* outp = (float*)d_out;

    prep_kernel<<<(NPTS + 255) / 256, 256>>>(p);
    gemm3_kernel<<<dim3(NPTS / 64, 3), 256>>>(x, Wq, bq, Wk, bk, Wv, bv);
    knn_kernel<<<NPTS / 8, 256>>>();
    attn_kernel<<<NPTS, 256>>>(outp, Wp1, bp1, g1, be1, Wp2, bp2,
                               g2, be2, Ww1, bw1, g3, be3, Ww2, bw2);
}

// round 4
// speedup vs baseline: 2.0896x; 1.0198x over previous
#include <cuda_runtime.h>
#include <float.h>
#include <math.h>

#define NPTS 8192
#define CDIM 128
#define KNN  16
#define CS   16            // C / S
#define BN_INV 0.99999500003749973f   // 1/sqrt(1 + 1e-5)
#define TS   2048          // knn point tile (32 KB)

// ---------------- scratch (static device globals; no allocation) ----------------
static __device__ float4 g_p4[NPTS];
static __device__ int    g_idx[NPTS * KNN];
static __device__ float  g_d2 [NPTS * KNN];
static __device__ float  g_xq [NPTS * CDIM];
static __device__ float  g_xk [NPTS * CDIM];
static __device__ float  g_xv [NPTS * CDIM];

// ---------------- kernel 0: pack p into float4 (x,y,z,|p|^2) ----------------
__global__ void prep_kernel(const float* __restrict__ p) {
    int i = blockIdx.x * blockDim.x + threadIdx.x;
    if (i < NPTS) {
        float x = p[i * 3 + 0], y = p[i * 3 + 1], z = p[i * 3 + 2];
        g_p4[i] = make_float4(x, y, z, x * x + y * y + z * z);
    }
}

// ---------------- kernel 1: KNN v5 — warp/query streaming top-16, 4-pt unroll ----------------
__device__ __forceinline__ void knn_insert(float cv, int cj, float& kv, int& ki,
                                           float& kthv, int& kthi, int lane) {
    // skip if list already improved past this candidate (uniform)
    if (!((cv < kthv) || (cv == kthv && cj < kthi))) return;
    const bool lt = (kv < cv) || (kv == cv && ki < cj);
    const int pos = __popc(__ballot_sync(0xffffffffu, lt) & 0xFFFFu);
    const float upv = __shfl_up_sync(0xffffffffu, kv, 1);
    const int   upi = __shfl_up_sync(0xffffffffu, ki, 1);
    if (lane >= pos && lane < 16) {
        if (lane == pos) { kv = cv; ki = cj; }
        else             { kv = upv; ki = upi; }
    }
    kthv = __shfl_sync(0xffffffffu, kv, 15);
    kthi = __shfl_sync(0xffffffffu, ki, 15);
}

__global__ __launch_bounds__(256) void knn_kernel() {
    __shared__ float4 s_tile[TS];

    const int t    = threadIdx.x;
    const int w    = t >> 5;
    const int lane = t & 31;
    const int n    = blockIdx.x * 8 + w;

    const float4 q = g_p4[n];

    float kv = FLT_MAX;
    int   ki = 0x7FFFFFFF;
    float kthv = FLT_MAX;
    int   kthi = 0x7FFFFFFF;

    for (int tb = 0; tb < NPTS; tb += TS) {
        __syncthreads();
        #pragma unroll
        for (int i = 0; i < TS / 256; ++i)
            s_tile[t + i * 256] = g_p4[tb + t + i * 256];
        __syncthreads();

        for (int c = 0; c < TS / 128; ++c) {
            const int base = c * 128 + lane;
            float4 p0 = s_tile[base];
            float4 p1 = s_tile[base + 32];
            float4 p2 = s_tile[base + 64];
            float4 p3 = s_tile[base + 96];
            float d0 = (q.w + p0.w) - 2.0f * fmaf(q.x, p0.x, fmaf(q.y, p0.y, q.z * p0.z));
            float d1 = (q.w + p1.w) - 2.0f * fmaf(q.x, p1.x, fmaf(q.y, p1.y, q.z * p1.z));
            float d2 = (q.w + p2.w) - 2.0f * fmaf(q.x, p2.x, fmaf(q.y, p2.y, q.z * p2.z));
            float d3 = (q.w + p3.w) - 2.0f * fmaf(q.x, p3.x, fmaf(q.y, p3.y, q.z * p3.z));
            const int j0 = tb + base, j1 = j0 + 32, j2 = j0 + 64, j3 = j0 + 96;

            bool pass0 = (d0 < kthv) || (d0 == kthv && j0 < kthi);
            bool pass1 = (d1 < kthv) || (d1 == kthv && j1 < kthi);
            bool pass2 = (d2 < kthv) || (d2 == kthv && j2 < kthi);
            bool pass3 = (d3 < kthv) || (d3 == kthv && j3 < kthi);
            unsigned any = __ballot_sync(0xffffffffu, pass0 | pass1 | pass2 | pass3);
            if (any) {
                unsigned m0 = __ballot_sync(0xffffffffu, pass0);
                while (m0) {
                    int src = __ffs(m0) - 1; m0 &= m0 - 1;
                    knn_insert(__shfl_sync(0xffffffffu, d0, src),
                               __shfl_sync(0xffffffffu, j0, src), kv, ki, kthv, kthi, lane);
                }
                unsigned m1 = __ballot_sync(0xffffffffu, pass1);
                while (m1) {
                    int src = __ffs(m1) - 1; m1 &= m1 - 1;
                    knn_insert(__shfl_sync(0xffffffffu, d1, src),
                               __shfl_sync(0xffffffffu, j1, src), kv, ki, kthv, kthi, lane);
                }
                unsigned m2 = __ballot_sync(0xffffffffu, pass2);
                while (m2) {
                    int src = __ffs(m2) - 1; m2 &= m2 - 1;
                    knn_insert(__shfl_sync(0xffffffffu, d2, src),
                               __shfl_sync(0xffffffffu, j2, src), kv, ki, kthv, kthi, lane);
                }
                unsigned m3 = __ballot_sync(0xffffffffu, pass3);
                while (m3) {
                    int src = __ffs(m3) - 1; m3 &= m3 - 1;
                    knn_insert(__shfl_sync(0xffffffffu, d3, src),
                               __shfl_sync(0xffffffffu, j3, src), kv, ki, kthv, kthi, lane);
                }
            }
        }
    }

    if (lane < KNN) {
        g_d2 [n * KNN + lane] = kv;
        g_idx[n * KNN + lane] = ki;
    }
}

// ---------------- kernel 2: three 8192x128x128 fp32 GEMMs (xq,xk,xv) ----------------
__global__ __launch_bounds__(256, 2) void gemm3_kernel(
    const float* __restrict__ x,
    const float* __restrict__ Wq, const float* __restrict__ bq,
    const float* __restrict__ Wk, const float* __restrict__ bk,
    const float* __restrict__ Wv, const float* __restrict__ bv)
{
    __shared__ float  As[64][17];
    __shared__ float4 Bs[16][32];   // 16 x 128 floats

    const float* W; const float* b; float* out;
    if (blockIdx.y == 0)      { W = Wq; b = bq; out = g_xq; }
    else if (blockIdx.y == 1) { W = Wk; b = bk; out = g_xk; }
    else                      { W = Wv; b = bv; out = g_xv; }

    const int t  = threadIdx.x;
    const int tx = t & 15, ty = t >> 4;
    const int row0 = blockIdx.x * 64;

    float acc[4][8];
    #pragma unroll
    for (int i = 0; i < 4; ++i)
        #pragma unroll
        for (int j = 0; j < 8; ++j) acc[i][j] = 0.0f;

    for (int k0 = 0; k0 < CDIM; k0 += 16) {
        #pragma unroll
        for (int i = 0; i < 4; ++i) {
            int lin = t + i * 256;
            int r = lin >> 4, kk = lin & 15;
            As[r][kk] = x[(row0 + r) * CDIM + k0 + kk];
        }
        #pragma unroll
        for (int i = 0; i < 8; ++i) {
            int lin = t + i * 256;
            int kk = lin >> 7, col = lin & 127;
            ((float*)Bs)[kk * 128 + col] = W[(k0 + kk) * CDIM + col];
        }
        __syncthreads();
        #pragma unroll
        for (int kk = 0; kk < 16; ++kk) {
            float a[4];
            #pragma unroll
            for (int i = 0; i < 4; ++i) a[i] = As[ty * 4 + i][kk];
            float4 b0 = Bs[kk][tx * 2 + 0];
            float4 b1 = Bs[kk][tx * 2 + 1];
            float bb[8] = {b0.x, b0.y, b0.z, b0.w, b1.x, b1.y, b1.z, b1.w};
            #pragma unroll
            for (int i = 0; i < 4; ++i)
                #pragma unroll
                for (int j = 0; j < 8; ++j)
                    acc[i][j] = fmaf(a[i], bb[j], acc[i][j]);
        }
        __syncthreads();
    }
    #pragma unroll
    for (int i = 0; i < 4; ++i) {
        int r = row0 + ty * 4 + i;
        #pragma unroll
        for (int j = 0; j < 8; ++j) {
            int c = tx * 8 + j;
            out[r * CDIM + c] = acc[i][j] + __ldg(&b[c]);
        }
    }
}

// ---------------- kernel 3: attn v3 — 2 queries/block, 4 neighbors/warp ----------------
#define PITCH 132   // 132*4 = 528 bytes, 16B aligned

// value-splitting butterfly over 32 distributed values; final lane l holds value index l
__device__ __forceinline__ float reduce32(float red[32], int l) {
    #pragma unroll
    for (int i = 0; i < 16; ++i) {
        bool hi = (l & 16) != 0;
        float send = hi ? red[i] : red[i + 16];
        float recv = __shfl_xor_sync(0xffffffffu, send, 16);
        red[i] = (hi ? red[i + 16] : red[i]) + recv;
    }
    #pragma unroll
    for (int i = 0; i < 8; ++i) {
        bool hi = (l & 8) != 0;
        float send = hi ? red[i] : red[i + 8];
        float recv = __shfl_xor_sync(0xffffffffu, send, 8);
        red[i] = (hi ? red[i + 8] : red[i]) + recv;
    }
    #pragma unroll
    for (int i = 0; i < 4; ++i) {
        bool hi = (l & 4) != 0;
        float send = hi ? red[i] : red[i + 4];
        float recv = __shfl_xor_sync(0xffffffffu, send, 4);
        red[i] = (hi ? red[i + 4] : red[i]) + recv;
    }
    #pragma unroll
    for (int i = 0; i < 2; ++i) {
        bool hi = (l & 2) != 0;
        float send = hi ? red[i] : red[i + 2];
        float recv = __shfl_xor_sync(0xffffffffu, send, 2);
        red[i] = (hi ? red[i + 2] : red[i]) + recv;
    }
    {
        bool hi = (l & 1) != 0;
        float send = hi ? red[0] : red[1];
        float recv = __shfl_xor_sync(0xffffffffu, send, 1);
        red[0] = (hi ? red[1] : red[0]) + recv;
    }
    return red[0];
}

__global__ __launch_bounds__(256) void attn_kernel(
    float* __restrict__ outp,
    const float* __restrict__ Wp1, const float* __restrict__ bp1,
    const float* __restrict__ g1,  const float* __restrict__ be1,
    const float* __restrict__ Wp2, const float* __restrict__ bp2,
    const float* __restrict__ g2,  const float* __restrict__ be2,
    const float* __restrict__ Ww1, const float* __restrict__ bw1,
    const float* __restrict__ g3,  const float* __restrict__ be3,
    const float* __restrict__ Ww2, const float* __restrict__ bw2)
{
    __shared__ float s_w1t[CS][PITCH];       // Ww1 transposed: [j][c]
    __shared__ float s_v  [2][KNN][PITCH];   // v = xv*dw + pr, per query
    __shared__ float s_ww2[CS][CS];
    __shared__ float s_pr1[2][KNN][4];
    __shared__ float s_dw [2][KNN];
    __shared__ int   s_id [2][KNN];
    __shared__ float s_h  [2][KNN][17];
    __shared__ float s_w2 [2][KNN][17];

    const int n0 = blockIdx.x * 2;
    const int t  = threadIdx.x;
    const int w  = t >> 5;          // warp 0..7
    const int q  = w >> 2;          // query slot 0/1
    const int wq = w & 3;           // warp within query
    const int l  = t & 31;

    // stage Ww1^T and Ww2
    #pragma unroll
    for (int i = t; i < CDIM * CS; i += 256) {
        int c = i >> 4, j = i & 15;
        s_w1t[j][c] = Ww1[i];
    }
    s_ww2[t >> 4][t & 15] = Ww2[t];

    // phase A: per-neighbor scalars for both queries (32 threads)
    if (t < 32) {
        const int qa = t >> 4, kk = t & 15;
        const int n = n0 + qa;
        int id = g_idx[n * KNN + kk];
        s_id[qa][kk] = id;
        float d2 = g_d2[n * KNN + kk];
        s_dw[qa][kk] = expf(-sqrtf(fmaxf(d2, 0.0f)));
        float4 pq = g_p4[n], pj = g_p4[id];
        float rx = pj.x - pq.x, ry = pj.y - pq.y, rz = pj.z - pq.z;
        #pragma unroll
        for (int j = 0; j < 3; ++j) {
            float vv = rx * Wp1[0 * 3 + j] + ry * Wp1[1 * 3 + j] + rz * Wp1[2 * 3 + j] + bp1[j];
            vv = vv * (g1[j] * BN_INV) + be1[j];
            s_pr1[qa][kk][j] = fmaxf(vv, 0.0f);
        }
    }
    __syncthreads();

    // phase B: warp handles 4 neighbors (k = 4*wq + u) of query n0+q; lane owns channels 4l..4l+3
    const int n = n0 + q;
    const int c0 = 4 * l;
    float4 w0[4];
    {
        const float4 xq4 = *(const float4*)&g_xq[n * CDIM + c0];
        const float4 wpA = *(const float4*)&Wp2[0 * CDIM + c0];
        const float4 wpB = *(const float4*)&Wp2[1 * CDIM + c0];
        const float4 wpC = *(const float4*)&Wp2[2 * CDIM + c0];
        const float4 bp4 = *(const float4*)&bp2[c0];
        float4 sc24 = *(const float4*)&g2[c0];
        sc24.x *= BN_INV; sc24.y *= BN_INV; sc24.z *= BN_INV; sc24.w *= BN_INV;
        const float4 be24 = *(const float4*)&be2[c0];

        #pragma unroll
        for (int u = 0; u < 4; ++u) {
            const int k = 4 * wq + u;
            const int id = s_id[q][k];
            const float4 xk4 = *(const float4*)&g_xk[id * CDIM + c0];
            const float4 xv4 = *(const float4*)&g_xv[id * CDIM + c0];
            const float a0 = s_pr1[q][k][0], a1 = s_pr1[q][k][1], a2 = s_pr1[q][k][2];
            const float dwv = s_dw[q][k];
            float4 pr;
            pr.x = fmaf(a0, wpA.x, fmaf(a1, wpB.x, fmaf(a2, wpC.x, bp4.x)));
            pr.y = fmaf(a0, wpA.y, fmaf(a1, wpB.y, fmaf(a2, wpC.y, bp4.y)));
            pr.z = fmaf(a0, wpA.z, fmaf(a1, wpB.z, fmaf(a2, wpC.z, bp4.z)));
            pr.w = fmaf(a0, wpA.w, fmaf(a1, wpB.w, fmaf(a2, wpC.w, bp4.w)));
            float4 v4;
            v4.x = fmaf(xv4.x, dwv, pr.x); v4.y = fmaf(xv4.y, dwv, pr.y);
            v4.z = fmaf(xv4.z, dwv, pr.z); v4.w = fmaf(xv4.w, dwv, pr.w);
            *(float4*)&s_v[q][k][c0] = v4;
            w0[u].x = fmaxf(fmaf(xq4.x - xk4.x + pr.x, sc24.x, be24.x), 0.0f);
            w0[u].y = fmaxf(fmaf(xq4.y - xk4.y + pr.y, sc24.y, be24.y), 0.0f);
            w0[u].z = fmaxf(fmaf(xq4.z - xk4.z + pr.z, sc24.z, be24.z), 0.0f);
            w0[u].w = fmaxf(fmaf(xq4.w - xk4.w + pr.w, sc24.w, be24.w), 0.0f);
        }
    }

    // two passes over j-halves: partials for 4 neighbors x 8 j, butterfly-reduced
    #pragma unroll
    for (int jb = 0; jb < 16; jb += 8) {
        float red[32];
        #pragma unroll
        for (int j = 0; j < 8; ++j) {
            const float4 wv = *(const float4*)&s_w1t[jb + j][c0];
            #pragma unroll
            for (int u = 0; u < 4; ++u) {
                red[u * 8 + j] = w0[u].x * wv.x + w0[u].y * wv.y
                               + w0[u].z * wv.z + w0[u].w * wv.w;
            }
        }
        const float sum = reduce32(red, l);
        // lane l holds value index l: u = l>>3, j_local = l&7
        const int jj = jb + (l & 7);
        const int kk = 4 * wq + (l >> 3);
        const float val = sum + __ldg(&bw1[jj]);
        s_h[q][kk][jj] = fmaxf(fmaf(val, __ldg(&g3[jj]) * BN_INV, __ldg(&be3[jj])), 0.0f);
    }
    __syncthreads();

    // w2 = h @ Ww2, softmax over k — both queries handled by all 256 threads
    const int k16 = t >> 4, j16 = t & 15;
    #pragma unroll
    for (int qq = 0; qq < 2; ++qq) {
        float acc2 = __ldg(&bw2[j16]);
        #pragma unroll
        for (int j2 = 0; j2 < CS; ++j2)
            acc2 = fmaf(s_h[qq][k16][j2], s_ww2[j2][j16], acc2);
        s_w2[qq][k16][j16] = acc2;
    }
    __syncthreads();
    #pragma unroll
    for (int qq = 0; qq < 2; ++qq) {
        float m = -FLT_MAX;
        #pragma unroll
        for (int k2 = 0; k2 < KNN; ++k2) m = fmaxf(m, s_w2[qq][k2][j16]);
        s_h[qq][k16][j16] = expf(s_w2[qq][k16][j16] - m);
    }
    __syncthreads();
    #pragma unroll
    for (int qq = 0; qq < 2; ++qq) {
        float ssum = 0.0f;
        #pragma unroll
        for (int k2 = 0; k2 < KNN; ++k2) ssum += s_h[qq][k2][j16];
        s_w2[qq][k16][j16] = s_h[qq][k16][j16] / ssum;
    }
    __syncthreads();

    // phase D: q = t>>7, c = t&127
    {
        const int qd = t >> 7;
        const int c  = t & 127;
        const int jj = c & 15;
        float o = 0.0f;
        #pragma unroll
        for (int k2 = 0; k2 < KNN; ++k2)
            o = fmaf(s_v[qd][k2][c], s_w2[qd][k2][jj], o);
        outp[(n0 + qd) * CDIM + c] = o;
    }
}

// ---------------- launch: gemm on side stream, overlapped with prep+knn ----------------
extern "C" void kernel_launch(void* const* d_in, const int* in_sizes, int n_in,
                              void* d_out, int out_size) {
    const float* p   = (const float*)d_in[0];
    const float* x   = (const float*)d_in[1];
    const float* Wq  = (const float*)d_in[2];
    const float* bq  = (const float*)d_in[3];
    const float* Wk  = (const float*)d_in[4];
    const float* bk  = (const float*)d_in[5];
    const float* Wv  = (const float*)d_in[6];
    const float* bv  = (const float*)d_in[7];
    const float* Wp1 = (const float*)d_in[8];
    const float* bp1 = (const float*)d_in[9];
    const float* g1  = (const float*)d_in[10];
    const float* be1 = (const float*)d_in[11];
    const float* Wp2 = (const float*)d_in[12];
    const float* bp2 = (const float*)d_in[13];
    const float* g2  = (const float*)d_in[14];
    const float* be2 = (const float*)d_in[15];
    const float* Ww1 = (const float*)d_in[16];
    const float* bw1 = (const float*)d_in[17];
    const float* g3  = (const float*)d_in[18];
    const float* be3 = (const float*)d_in[19];
    const float* Ww2 = (const float*)d_in[20];
    const float* bw2 = (const float*)d_in[21];
    float* outp = (float*)d_out;

    // side stream + events; created per call (kernel_launch runs only for
    // correctness + capture), no device memory involved, never destroyed.
    cudaStream_t s2;
    cudaStreamCreateWithFlags(&s2, cudaStreamNonBlocking);
    cudaEvent_t evStart, evG;
    cudaEventCreateWithFlags(&evStart, cudaEventDisableTiming);
    cudaEventCreateWithFlags(&evG, cudaEventDisableTiming);

    cudaEventRecord(evStart, 0);
    cudaStreamWaitEvent(s2, evStart, 0);
    gemm3_kernel<<<dim3(NPTS / 64, 3), 256, 0, s2>>>(x, Wq, bq, Wk, bk, Wv, bv);
    cudaEventRecord(evG, s2);

    prep_kernel<<<(NPTS + 255) / 256, 256>>>(p);
    knn_kernel<<<NPTS / 8, 256>>>();

    cudaStreamWaitEvent(0, evG, 0);
    attn_kernel<<<NPTS / 2, 256>>>(outp, Wp1, bp1, g1, be1, Wp2, bp2,
                                   g2, be2, Ww1, bw1, g3, be3, Ww2, bw2);
}